// round 1
// baseline (speedup 1.0000x reference)
#include <cuda_runtime.h>
#include <math.h>

// Problem constants (match reference setup_inputs)
#define NUM_SEQS   64
#define NUM_HEADS  32
#define KVH        8
#define GQ         4      // query heads per kv head
#define HD         128    // head size
#define BS         16     // paged block size
#define MAXL       2048
#define MAXB       128    // max blocks per seq
#define CHUNK      64     // tokens per iteration
#define NTHREADS   256

__global__ __launch_bounds__(NTHREADS)
void paged_attn_kernel(const float* __restrict__ q,
                       const float* __restrict__ kcache,
                       const float* __restrict__ vcache,
                       const float* __restrict__ scale_p,
                       const int*   __restrict__ btab,
                       const int*   __restrict__ seqlen,
                       const float* __restrict__ slopes,
                       float*       __restrict__ out)
{
    const int s    = blockIdx.x / KVH;
    const int kv   = blockIdx.x % KVH;
    const int tid  = threadIdx.x;
    const int lane = tid & 31;
    const int warp = tid >> 5;

    const int len = seqlen[s];
    const float scale = scale_p[0];

    __shared__ float q_s[GQ][HD];
    __shared__ float sc[GQ][CHUNK];
    __shared__ int   blk[MAXB];
    __shared__ float m_s[GQ], l_s[GQ], corr_s[GQ];

    // Load Q (4 heads x 128), pre-scaled
    for (int i = tid; i < GQ * HD; i += NTHREADS) {
        int g = i >> 7, d = i & 127;
        q_s[g][d] = q[(s * NUM_HEADS + kv * GQ + g) * HD + d] * scale;
    }
    // Stage block table
    const int nblk = (len + BS - 1) / BS;
    for (int i = tid; i < nblk; i += NTHREADS) blk[i] = btab[s * MAXB + i];
    if (tid < GQ) { m_s[tid] = -1e30f; l_s[tid] = 0.0f; }
    __syncthreads();

    // Per-warp register copy of Q (each lane: float4 at d = 4*lane, all 4 heads)
    float4 qr0 = ((const float4*)q_s[0])[lane];
    float4 qr1 = ((const float4*)q_s[1])[lane];
    float4 qr2 = ((const float4*)q_s[2])[lane];
    float4 qr3 = ((const float4*)q_s[3])[lane];

    // ALiBi slopes for this kv-head's 4 query heads
    float slp0 = slopes[kv * GQ + 0];
    float slp1 = slopes[kv * GQ + 1];
    float slp2 = slopes[kv * GQ + 2];
    float slp3 = slopes[kv * GQ + 3];

    // Accumulators: thread owns (g0, d) and (g0+2, d)
    const int d  = tid & 127;
    const int g0 = tid >> 7;        // 0 or 1
    float acc0 = 0.0f, acc1 = 0.0f;

    for (int base = 0; base < len; base += CHUNK) {
        // ---- Phase 1: scores for tokens [base, base+CHUNK) ----
        for (int tl = warp; tl < CHUNK; tl += 8) {
            const int t = base + tl;
            if (t < len) {
                const int b = blk[t >> 4];
                const float4* krow = (const float4*)
                    (kcache + ((size_t)((b * KVH + kv) * BS + (t & 15))) * HD);
                float4 k4 = krow[lane];
                float p0 = qr0.x*k4.x + qr0.y*k4.y + qr0.z*k4.z + qr0.w*k4.w;
                float p1 = qr1.x*k4.x + qr1.y*k4.y + qr1.z*k4.z + qr1.w*k4.w;
                float p2 = qr2.x*k4.x + qr2.y*k4.y + qr2.z*k4.z + qr2.w*k4.w;
                float p3 = qr3.x*k4.x + qr3.y*k4.y + qr3.z*k4.z + qr3.w*k4.w;
                #pragma unroll
                for (int off = 16; off > 0; off >>= 1) {
                    p0 += __shfl_xor_sync(0xffffffff, p0, off);
                    p1 += __shfl_xor_sync(0xffffffff, p1, off);
                    p2 += __shfl_xor_sync(0xffffffff, p2, off);
                    p3 += __shfl_xor_sync(0xffffffff, p3, off);
                }
                if (lane == 0) {
                    const float rel = (float)(t - (len - 1));
                    sc[0][tl] = p0 + slp0 * rel;
                    sc[1][tl] = p1 + slp1 * rel;
                    sc[2][tl] = p2 + slp2 * rel;
                    sc[3][tl] = p3 + slp3 * rel;
                }
            } else if (lane == 0) {
                sc[0][tl] = -1e30f; sc[1][tl] = -1e30f;
                sc[2][tl] = -1e30f; sc[3][tl] = -1e30f;
            }
        }
        __syncthreads();

        // ---- Phase 2: online softmax (warp g handles head g) ----
        if (warp < GQ) {
            float mx = -1e30f;
            #pragma unroll
            for (int i = lane; i < CHUNK; i += 32) mx = fmaxf(mx, sc[warp][i]);
            #pragma unroll
            for (int off = 16; off > 0; off >>= 1)
                mx = fmaxf(mx, __shfl_xor_sync(0xffffffff, mx, off));
            const float m_old = m_s[warp];
            const float m_new = fmaxf(m_old, mx);
            float sum = 0.0f;
            #pragma unroll
            for (int i = lane; i < CHUNK; i += 32) {
                float p = __expf(sc[warp][i] - m_new);
                sc[warp][i] = p;
                sum += p;
            }
            #pragma unroll
            for (int off = 16; off > 0; off >>= 1)
                sum += __shfl_xor_sync(0xffffffff, sum, off);
            if (lane == 0) {
                const float c = __expf(m_old - m_new);
                corr_s[warp] = c;
                l_s[warp] = l_s[warp] * c + sum;
                m_s[warp] = m_new;
            }
        }
        __syncthreads();

        // ---- Phase 3: V accumulation ----
        acc0 *= corr_s[g0];
        acc1 *= corr_s[g0 + 2];
        const int tmax = min(CHUNK, len - base);
        #pragma unroll 4
        for (int tl = 0; tl < tmax; tl++) {
            const int t = base + tl;
            const int b = blk[t >> 4];
            const float v = vcache[(size_t)((b * KVH + kv) * BS + (t & 15)) * HD + d];
            acc0 += sc[g0][tl] * v;
            acc1 += sc[g0 + 2][tl] * v;
        }
        __syncthreads();   // protect sc before next chunk overwrites it
    }

    // ---- Epilogue ----
    const float inv0 = 1.0f / l_s[g0];
    const float inv1 = 1.0f / l_s[g0 + 2];
    out[(s * NUM_HEADS + kv * GQ + g0)       * HD + d] = acc0 * inv0;
    out[(s * NUM_HEADS + kv * GQ + g0 + 2)   * HD + d] = acc1 * inv1;
}

extern "C" void kernel_launch(void* const* d_in, const int* in_sizes, int n_in,
                              void* d_out, int out_size) {
    const float* query       = (const float*)d_in[0];
    const float* key_cache   = (const float*)d_in[1];
    const float* value_cache = (const float*)d_in[2];
    // d_in[3] = num_kv_heads (known constant 8)
    const float* scale       = (const float*)d_in[4];
    const int*   block_tab   = (const int*)  d_in[5];
    const int*   seq_lens    = (const int*)  d_in[6];
    // d_in[7] = block_size (16), d_in[8] = max_seq_len (2048)
    const float* alibi       = (const float*)d_in[9];
    float* out = (float*)d_out;

    dim3 grid(NUM_SEQS * KVH);
    paged_attn_kernel<<<grid, NTHREADS>>>(query, key_cache, value_cache,
                                          scale, block_tab, seq_lens,
                                          alibi, out);
}

// round 2
// speedup vs baseline: 3.4317x; 3.4317x over previous
#include <cuda_runtime.h>
#include <math.h>

#define NUM_SEQS   64
#define NUM_HEADS  32
#define KVH        8
#define GQ         4      // query heads per kv head
#define HD         128    // head size
#define BS         16     // paged block size
#define MAXL       2048
#define MAXB       128    // max blocks per seq
#define CHUNK      64     // tokens per inner iteration
#define PART       256    // tokens per split-KV partition
#define NP         (MAXL / PART)   // 8 max partitions
#define NTHREADS   256

// Split-KV scratch (device globals: no allocation allowed in kernel_launch)
__device__ float g_pacc[NUM_SEQS * KVH * NP * GQ * HD];  // 8 MB
__device__ float g_pm[NUM_SEQS * KVH * NP * GQ];
__device__ float g_pl[NUM_SEQS * KVH * NP * GQ];

__global__ __launch_bounds__(NTHREADS)
void paged_attn_part_kernel(const float* __restrict__ q,
                            const float* __restrict__ kcache,
                            const float* __restrict__ vcache,
                            const float* __restrict__ scale_p,
                            const int*   __restrict__ btab,
                            const int*   __restrict__ seqlen,
                            const float* __restrict__ slopes)
{
    const int p    = blockIdx.x % NP;
    const int kv   = (blockIdx.x / NP) % KVH;
    const int s    = blockIdx.x / (NP * KVH);
    const int tid  = threadIdx.x;
    const int lane = tid & 31;
    const int warp = tid >> 5;

    const int len = seqlen[s];
    const int t0  = p * PART;
    if (t0 >= len) return;                 // inactive partition
    const int t1  = min(len, t0 + PART);
    const float scale = scale_p[0];

    __shared__ float q_s[GQ][HD];
    __shared__ float sc[GQ][CHUNK];
    __shared__ int   blk[PART / BS];       // 16 blocks per partition
    __shared__ float m_s[GQ], l_s[GQ], corr_s[GQ];

    for (int i = tid; i < GQ * HD; i += NTHREADS) {
        int g = i >> 7, d = i & 127;
        q_s[g][d] = q[(s * NUM_HEADS + kv * GQ + g) * HD + d] * scale;
    }
    const int blk0 = t0 >> 4;
    const int nblk = ((t1 + BS - 1) >> 4) - blk0;
    for (int i = tid; i < nblk; i += NTHREADS) blk[i] = btab[s * MAXB + blk0 + i];
    if (tid < GQ) { m_s[tid] = -1e30f; l_s[tid] = 0.0f; }
    __syncthreads();

    float4 qr0 = ((const float4*)q_s[0])[lane];
    float4 qr1 = ((const float4*)q_s[1])[lane];
    float4 qr2 = ((const float4*)q_s[2])[lane];
    float4 qr3 = ((const float4*)q_s[3])[lane];

    const float slp0 = slopes[kv * GQ + 0];
    const float slp1 = slopes[kv * GQ + 1];
    const float slp2 = slopes[kv * GQ + 2];
    const float slp3 = slopes[kv * GQ + 3];

    const int d  = tid & 127;
    const int g0 = tid >> 7;               // 0 or 1; thread owns heads g0 and g0+2
    float acc0 = 0.0f, acc1 = 0.0f;

    for (int base = t0; base < t1; base += CHUNK) {
        const int tmax = min(CHUNK, t1 - base);

        // ---- Phase 1: QK scores ----
        for (int tl = warp; tl < CHUNK; tl += 8) {
            const int t = base + tl;
            if (tl < tmax) {
                const int b = blk[(t >> 4) - blk0];
                const float4* krow = (const float4*)
                    (kcache + ((size_t)((b * KVH + kv) * BS + (t & 15))) * HD);
                float4 k4 = krow[lane];
                float p0 = qr0.x*k4.x + qr0.y*k4.y + qr0.z*k4.z + qr0.w*k4.w;
                float p1 = qr1.x*k4.x + qr1.y*k4.y + qr1.z*k4.z + qr1.w*k4.w;
                float p2 = qr2.x*k4.x + qr2.y*k4.y + qr2.z*k4.z + qr2.w*k4.w;
                float p3 = qr3.x*k4.x + qr3.y*k4.y + qr3.z*k4.z + qr3.w*k4.w;
                #pragma unroll
                for (int off = 16; off > 0; off >>= 1) {
                    p0 += __shfl_xor_sync(0xffffffff, p0, off);
                    p1 += __shfl_xor_sync(0xffffffff, p1, off);
                    p2 += __shfl_xor_sync(0xffffffff, p2, off);
                    p3 += __shfl_xor_sync(0xffffffff, p3, off);
                }
                if (lane == 0) {
                    const float rel = (float)(t - (len - 1));
                    sc[0][tl] = p0 + slp0 * rel;
                    sc[1][tl] = p1 + slp1 * rel;
                    sc[2][tl] = p2 + slp2 * rel;
                    sc[3][tl] = p3 + slp3 * rel;
                }
            } else if (lane == 0) {
                sc[0][tl] = -1e30f; sc[1][tl] = -1e30f;
                sc[2][tl] = -1e30f; sc[3][tl] = -1e30f;
            }
        }
        __syncthreads();

        // ---- Phase 2: online softmax (warp g -> head g) ----
        if (warp < GQ) {
            float mx = -1e30f;
            #pragma unroll
            for (int i = lane; i < CHUNK; i += 32) mx = fmaxf(mx, sc[warp][i]);
            #pragma unroll
            for (int off = 16; off > 0; off >>= 1)
                mx = fmaxf(mx, __shfl_xor_sync(0xffffffff, mx, off));
            const float m_old = m_s[warp];
            const float m_new = fmaxf(m_old, mx);
            float sum = 0.0f;
            #pragma unroll
            for (int i = lane; i < CHUNK; i += 32) {
                float pr = __expf(sc[warp][i] - m_new);
                sc[warp][i] = pr;
                sum += pr;
            }
            #pragma unroll
            for (int off = 16; off > 0; off >>= 1)
                sum += __shfl_xor_sync(0xffffffff, sum, off);
            if (lane == 0) {
                const float c = __expf(m_old - m_new);
                corr_s[warp] = c;
                l_s[warp] = l_s[warp] * c + sum;
                m_s[warp] = m_new;
            }
        }
        __syncthreads();

        // ---- Phase 3: V accumulation (batched loads, MLP=8) ----
        acc0 *= corr_s[g0];
        acc1 *= corr_s[g0 + 2];
        int tl = 0;
        for (; tl + 8 <= tmax; tl += 8) {
            float vv[8];
            #pragma unroll
            for (int j = 0; j < 8; j++) {
                const int t = base + tl + j;
                const int b = blk[(t >> 4) - blk0];
                vv[j] = vcache[(size_t)((b * KVH + kv) * BS + (t & 15)) * HD + d];
            }
            #pragma unroll
            for (int j = 0; j < 8; j++) {
                acc0 += sc[g0][tl + j]     * vv[j];
                acc1 += sc[g0 + 2][tl + j] * vv[j];
            }
        }
        for (; tl < tmax; tl++) {
            const int t = base + tl;
            const int b = blk[(t >> 4) - blk0];
            const float v = vcache[(size_t)((b * KVH + kv) * BS + (t & 15)) * HD + d];
            acc0 += sc[g0][tl]     * v;
            acc1 += sc[g0 + 2][tl] * v;
        }
        __syncthreads();
    }

    // ---- Write partials (unnormalized acc, per-head m and l) ----
    const size_t pb = ((size_t)(s * KVH + kv) * NP + p) * GQ;
    g_pacc[(pb + g0)     * HD + d] = acc0;
    g_pacc[(pb + g0 + 2) * HD + d] = acc1;
    if (tid < GQ) {
        g_pm[pb + tid] = m_s[tid];
        g_pl[pb + tid] = l_s[tid];
    }
}

__global__ __launch_bounds__(NTHREADS)
void paged_attn_reduce_kernel(const int* __restrict__ seqlen,
                              float* __restrict__ out)
{
    const int s   = blockIdx.x / KVH;
    const int kv  = blockIdx.x % KVH;
    const int tid = threadIdx.x;
    const int d   = tid & 127;
    const int g0  = tid >> 7;

    const int len = seqlen[s];
    const int np  = (len + PART - 1) / PART;
    const size_t base = (size_t)(s * KVH + kv) * NP * GQ;

    #pragma unroll
    for (int gi = 0; gi < 2; gi++) {
        const int g = g0 + gi * 2;
        float M = -1e30f;
        for (int p = 0; p < np; p++)
            M = fmaxf(M, g_pm[base + (size_t)p * GQ + g]);
        float L = 0.0f, o = 0.0f;
        for (int p = 0; p < np; p++) {
            const size_t idx = base + (size_t)p * GQ + g;
            const float w = __expf(g_pm[idx] - M);
            L += w * g_pl[idx];
            o += w * g_pacc[idx * HD + d];
        }
        out[(s * NUM_HEADS + kv * GQ + g) * HD + d] = o / L;
    }
}

extern "C" void kernel_launch(void* const* d_in, const int* in_sizes, int n_in,
                              void* d_out, int out_size) {
    const float* query       = (const float*)d_in[0];
    const float* key_cache   = (const float*)d_in[1];
    const float* value_cache = (const float*)d_in[2];
    const float* scale       = (const float*)d_in[4];
    const int*   block_tab   = (const int*)  d_in[5];
    const int*   seq_lens    = (const int*)  d_in[6];
    const float* alibi       = (const float*)d_in[9];
    float* out = (float*)d_out;

    paged_attn_part_kernel<<<NUM_SEQS * KVH * NP, NTHREADS>>>(
        query, key_cache, value_cache, scale, block_tab, seq_lens, alibi);
    paged_attn_reduce_kernel<<<NUM_SEQS * KVH, NTHREADS>>>(seq_lens, out);
}

// round 3
// speedup vs baseline: 5.7294x; 1.6695x over previous
#include <cuda_runtime.h>
#include <math.h>

#define NUM_SEQS   64
#define NUM_HEADS  32
#define KVH        8
#define GQ         4      // query heads per kv head
#define HD         128    // head size
#define BS         16     // paged block size
#define MAXL       2048
#define MAXB       128    // max blocks per seq
#define PART       128    // tokens per split-KV partition (single chunk)
#define NP         (MAXL / PART)   // 16 partitions max
#define NTHREADS   256
#define NWARPS     8

// Split-KV scratch (device globals: no allocation allowed)
__device__ float g_pacc[NUM_SEQS * KVH * NP * GQ * HD];  // ~16.8 MB
__device__ float g_pm[NUM_SEQS * KVH * NP * GQ];
__device__ float g_pl[NUM_SEQS * KVH * NP * GQ];

__global__ __launch_bounds__(NTHREADS)
void paged_attn_part_kernel(const float* __restrict__ q,
                            const float* __restrict__ kcache,
                            const float* __restrict__ vcache,
                            const float* __restrict__ scale_p,
                            const int*   __restrict__ btab,
                            const int*   __restrict__ seqlen,
                            const float* __restrict__ slopes)
{
    const int p    = blockIdx.x % NP;
    const int kv   = (blockIdx.x / NP) % KVH;
    const int s    = blockIdx.x / (NP * KVH);
    const int tid  = threadIdx.x;
    const int lane = tid & 31;
    const int warp = tid >> 5;

    const int len = seqlen[s];
    const int t0  = p * PART;
    if (t0 >= len) return;
    const int tmax = min(PART, len - t0);
    const float scale = scale_p[0];

    __shared__ float red[NWARPS][GQ][HD];   // 16 KB; also stages Q at start
    __shared__ float sc[GQ][PART];          // 2 KB
    __shared__ int   blk[PART / BS];        // 8 blocks
    __shared__ float m_s[GQ], l_s[GQ];

    // Stage Q (scaled) into red[0..1]
    for (int i = tid; i < GQ * HD; i += NTHREADS) {
        int g = i >> 7, d = i & 127;
        red[0][0][i] = q[(s * NUM_HEADS + kv * GQ + g) * HD + d] * scale;
        (void)g; (void)d;
    }
    const int nblk = (tmax + BS - 1) >> 4;
    if (tid < nblk) blk[tid] = btab[s * MAXB + (t0 >> 4) + tid];
    __syncthreads();

    // Per-lane register Q: float4 at dims [4*lane, 4*lane+4) for each head
    float4 qr0 = ((const float4*)&red[0][0][0])[lane];
    float4 qr1 = ((const float4*)&red[0][1][0])[lane];
    float4 qr2 = ((const float4*)&red[0][2][0])[lane];
    float4 qr3 = ((const float4*)&red[0][3][0])[lane];
    __syncthreads();   // Q consumed; red free for reuse later

    const float slp0 = slopes[kv * GQ + 0];
    const float slp1 = slopes[kv * GQ + 1];
    const float slp2 = slopes[kv * GQ + 2];
    const float slp3 = slopes[kv * GQ + 3];

    const size_t kvbase = (size_t)kv * BS * HD;
    const size_t kvstride = (size_t)KVH * BS * HD;

    // ---- Phase 1: QK scores. Warp owns tokens tl = warp + 8j; batch loads x4 ----
    #pragma unroll
    for (int jb = 0; jb < 16; jb += 4) {
        float4 k4[4];
        #pragma unroll
        for (int u = 0; u < 4; u++) {
            const int tl = warp + (jb + u) * NWARPS;
            if (tl < tmax) {
                const int b = blk[tl >> 4];
                const float* krow = kcache + (size_t)b * kvstride + kvbase
                                  + (size_t)(tl & 15) * HD;
                k4[u] = ((const float4*)krow)[lane];
            }
        }
        #pragma unroll
        for (int u = 0; u < 4; u++) {
            const int tl = warp + (jb + u) * NWARPS;
            if (tl < tmax) {
                float p0 = qr0.x*k4[u].x + qr0.y*k4[u].y + qr0.z*k4[u].z + qr0.w*k4[u].w;
                float p1 = qr1.x*k4[u].x + qr1.y*k4[u].y + qr1.z*k4[u].z + qr1.w*k4[u].w;
                float p2 = qr2.x*k4[u].x + qr2.y*k4[u].y + qr2.z*k4[u].z + qr2.w*k4[u].w;
                float p3 = qr3.x*k4[u].x + qr3.y*k4[u].y + qr3.z*k4[u].z + qr3.w*k4[u].w;
                #pragma unroll
                for (int off = 16; off > 0; off >>= 1) {
                    p0 += __shfl_xor_sync(0xffffffff, p0, off);
                    p1 += __shfl_xor_sync(0xffffffff, p1, off);
                    p2 += __shfl_xor_sync(0xffffffff, p2, off);
                    p3 += __shfl_xor_sync(0xffffffff, p3, off);
                }
                if (lane == 0) {
                    const float rel = (float)(t0 + tl - (len - 1));
                    sc[0][tl] = p0 + slp0 * rel;
                    sc[1][tl] = p1 + slp1 * rel;
                    sc[2][tl] = p2 + slp2 * rel;
                    sc[3][tl] = p3 + slp3 * rel;
                }
            } else if (lane == 0) {
                sc[0][tl] = -1e30f; sc[1][tl] = -1e30f;
                sc[2][tl] = -1e30f; sc[3][tl] = -1e30f;
            }
        }
    }
    __syncthreads();

    // ---- Phase 2: softmax (warp g -> head g), single pass, no online update ----
    if (warp < GQ) {
        float mx = -1e30f;
        #pragma unroll
        for (int i = lane; i < PART; i += 32) mx = fmaxf(mx, sc[warp][i]);
        #pragma unroll
        for (int off = 16; off > 0; off >>= 1)
            mx = fmaxf(mx, __shfl_xor_sync(0xffffffff, mx, off));
        float sum = 0.0f;
        #pragma unroll
        for (int i = lane; i < PART; i += 32) {
            float pr = __expf(sc[warp][i] - mx);
            sc[warp][i] = pr;
            sum += pr;
        }
        #pragma unroll
        for (int off = 16; off > 0; off >>= 1)
            sum += __shfl_xor_sync(0xffffffff, sum, off);
        if (lane == 0) { m_s[warp] = mx; l_s[warp] = sum; }
    }
    __syncthreads();

    // ---- Phase 3: V accumulation. Warp owns tokens tl = warp + 8j.
    //      Lane holds float4 of dims; 4 per-head float4 accumulators. ----
    float4 a0 = {0,0,0,0}, a1 = {0,0,0,0}, a2 = {0,0,0,0}, a3 = {0,0,0,0};
    #pragma unroll
    for (int jb = 0; jb < 16; jb += 4) {
        float4 v4[4];
        #pragma unroll
        for (int u = 0; u < 4; u++) {
            const int tl = warp + (jb + u) * NWARPS;
            if (tl < tmax) {
                const int b = blk[tl >> 4];
                const float* vrow = vcache + (size_t)b * kvstride + kvbase
                                  + (size_t)(tl & 15) * HD;
                v4[u] = ((const float4*)vrow)[lane];
            }
        }
        #pragma unroll
        for (int u = 0; u < 4; u++) {
            const int tl = warp + (jb + u) * NWARPS;
            if (tl < tmax) {
                const float p0 = sc[0][tl], p1 = sc[1][tl];
                const float p2 = sc[2][tl], p3 = sc[3][tl];
                a0.x += p0*v4[u].x; a0.y += p0*v4[u].y; a0.z += p0*v4[u].z; a0.w += p0*v4[u].w;
                a1.x += p1*v4[u].x; a1.y += p1*v4[u].y; a1.z += p1*v4[u].z; a1.w += p1*v4[u].w;
                a2.x += p2*v4[u].x; a2.y += p2*v4[u].y; a2.z += p2*v4[u].z; a2.w += p2*v4[u].w;
                a3.x += p3*v4[u].x; a3.y += p3*v4[u].y; a3.z += p3*v4[u].z; a3.w += p3*v4[u].w;
            }
        }
    }

    // ---- Cross-warp reduction via smem ----
    ((float4*)&red[warp][0][0])[lane] = a0;
    ((float4*)&red[warp][1][0])[lane] = a1;
    ((float4*)&red[warp][2][0])[lane] = a2;
    ((float4*)&red[warp][3][0])[lane] = a3;
    __syncthreads();

    const int d  = tid & 127;
    const int g0 = tid >> 7;               // thread owns heads g0 and g0+2 at dim d
    float r0 = 0.0f, r1 = 0.0f;
    #pragma unroll
    for (int w = 0; w < NWARPS; w++) {
        r0 += red[w][g0][d];
        r1 += red[w][g0 + 2][d];
    }

    const size_t pb = ((size_t)(s * KVH + kv) * NP + p) * GQ;
    g_pacc[(pb + g0)     * HD + d] = r0;
    g_pacc[(pb + g0 + 2) * HD + d] = r1;
    if (tid < GQ) {
        g_pm[pb + tid] = m_s[tid];
        g_pl[pb + tid] = l_s[tid];
    }
}

__global__ __launch_bounds__(NTHREADS)
void paged_attn_reduce_kernel(const int* __restrict__ seqlen,
                              float* __restrict__ out)
{
    const int s   = blockIdx.x / KVH;
    const int kv  = blockIdx.x % KVH;
    const int tid = threadIdx.x;
    const int d   = tid & 127;
    const int g0  = tid >> 7;

    const int len = seqlen[s];
    const int np  = (len + PART - 1) / PART;
    const size_t base = (size_t)(s * KVH + kv) * NP * GQ;

    #pragma unroll
    for (int gi = 0; gi < 2; gi++) {
        const int g = g0 + gi * 2;
        float M = -1e30f;
        for (int p = 0; p < np; p++)
            M = fmaxf(M, g_pm[base + (size_t)p * GQ + g]);
        float L = 0.0f, o = 0.0f;
        for (int p = 0; p < np; p++) {
            const size_t idx = base + (size_t)p * GQ + g;
            const float w = __expf(g_pm[idx] - M);
            L += w * g_pl[idx];
            o += w * g_pacc[idx * HD + d];
        }
        out[(s * NUM_HEADS + kv * GQ + g) * HD + d] = o / L;
    }
}

extern "C" void kernel_launch(void* const* d_in, const int* in_sizes, int n_in,
                              void* d_out, int out_size) {
    const float* query       = (const float*)d_in[0];
    const float* key_cache   = (const float*)d_in[1];
    const float* value_cache = (const float*)d_in[2];
    const float* scale       = (const float*)d_in[4];
    const int*   block_tab   = (const int*)  d_in[5];
    const int*   seq_lens    = (const int*)  d_in[6];
    const float* alibi       = (const float*)d_in[9];
    float* out = (float*)d_out;

    paged_attn_part_kernel<<<NUM_SEQS * KVH * NP, NTHREADS>>>(
        query, key_cache, value_cache, scale, block_tab, seq_lens, alibi);
    paged_attn_reduce_kernel<<<NUM_SEQS * KVH, NTHREADS>>>(seq_lens, out);
}

// round 4
// speedup vs baseline: 6.1918x; 1.0807x over previous
#include <cuda_runtime.h>
#include <math.h>

#define NUM_SEQS   64
#define NUM_HEADS  32
#define KVH        8
#define GQ         4      // query heads per kv head
#define HD         128    // head size
#define BS         16     // paged block size
#define MAXL       2048
#define MAXB       128    // max blocks per seq
#define PART       128    // tokens per split-KV partition
#define NP         (MAXL / PART)   // 16
#define NTHREADS   256
#define NWARPS     8

// Split-KV scratch (device globals)
__device__ float g_pacc[NUM_SEQS * KVH * NP * GQ * HD];
__device__ float g_pl[NUM_SEQS * KVH * NP * GQ];

__global__ __launch_bounds__(NTHREADS)
void paged_attn_part_kernel(const float* __restrict__ q,
                            const float* __restrict__ kcache,
                            const float* __restrict__ vcache,
                            const float* __restrict__ scale_p,
                            const int*   __restrict__ btab,
                            const int*   __restrict__ seqlen,
                            const float* __restrict__ slopes)
{
    const int p    = blockIdx.x % NP;
    const int kv   = (blockIdx.x / NP) % KVH;
    const int s    = blockIdx.x / (NP * KVH);
    const int tid  = threadIdx.x;
    const int lane = tid & 31;
    const int warp = tid >> 5;

    const int len = seqlen[s];
    const int t0  = p * PART;
    if (t0 >= len) return;
    const int tmax = min(PART, len - t0);
    const float scale = scale_p[0];

    __shared__ float red[NWARPS][GQ][HD];   // 16 KB; stages Q at start
    __shared__ float wl[NWARPS][GQ];        // per-warp prob sums
    __shared__ int   blk[PART / BS];

    // Stage Q (scaled)
    for (int i = tid; i < GQ * HD; i += NTHREADS)
        red[0][0][i] = q[(s * NUM_HEADS + kv * GQ) * HD + i] * scale;
    const int nblk = (tmax + BS - 1) >> 4;
    if (tid < nblk) blk[tid] = btab[s * MAXB + (t0 >> 4) + tid];
    __syncthreads();

    const float4 qr0 = ((const float4*)&red[0][0][0])[lane];
    const float4 qr1 = ((const float4*)&red[0][1][0])[lane];
    const float4 qr2 = ((const float4*)&red[0][2][0])[lane];
    const float4 qr3 = ((const float4*)&red[0][3][0])[lane];
    __syncthreads();   // Q consumed; red reused for output reduction

    const float slp0 = slopes[kv * GQ + 0];
    const float slp1 = slopes[kv * GQ + 1];
    const float slp2 = slopes[kv * GQ + 2];
    const float slp3 = slopes[kv * GQ + 3];
    const float relbase = (float)(t0 - (len - 1));

    const size_t kvbase   = (size_t)kv * BS * HD;
    const size_t kvstride = (size_t)KVH * BS * HD;

    float4 a0 = {0,0,0,0}, a1 = {0,0,0,0}, a2 = {0,0,0,0}, a3 = {0,0,0,0};
    float l0 = 0.f, l1 = 0.f, l2 = 0.f, l3 = 0.f;

    // Fused, barrier-free main loop: warp owns tokens tl = warp + 8j.
    #pragma unroll
    for (int jb = 0; jb < 16; jb += 2) {
        const int tlA = warp + jb * NWARPS;
        const int tlB = tlA + NWARPS;
        const bool okA = tlA < tmax;
        const bool okB = tlB < tmax;

        float4 kA, kB, vA, vB;
        if (okA) {
            const size_t rowA = (size_t)blk[tlA >> 4] * kvstride + kvbase
                              + (size_t)(tlA & 15) * HD;
            kA = ((const float4*)(kcache + rowA))[lane];
            vA = ((const float4*)(vcache + rowA))[lane];
        }
        if (okB) {
            const size_t rowB = (size_t)blk[tlB >> 4] * kvstride + kvbase
                              + (size_t)(tlB & 15) * HD;
            kB = ((const float4*)(kcache + rowB))[lane];
            vB = ((const float4*)(vcache + rowB))[lane];
        }

        if (okA) {
            float p0 = qr0.x*kA.x + qr0.y*kA.y + qr0.z*kA.z + qr0.w*kA.w;
            float p1 = qr1.x*kA.x + qr1.y*kA.y + qr1.z*kA.z + qr1.w*kA.w;
            float p2 = qr2.x*kA.x + qr2.y*kA.y + qr2.z*kA.z + qr2.w*kA.w;
            float p3 = qr3.x*kA.x + qr3.y*kA.y + qr3.z*kA.z + qr3.w*kA.w;
            #pragma unroll
            for (int off = 16; off > 0; off >>= 1) {
                p0 += __shfl_xor_sync(0xffffffff, p0, off);
                p1 += __shfl_xor_sync(0xffffffff, p1, off);
                p2 += __shfl_xor_sync(0xffffffff, p2, off);
                p3 += __shfl_xor_sync(0xffffffff, p3, off);
            }
            const float rel = relbase + (float)tlA;
            const float e0 = __expf(p0 + slp0 * rel);
            const float e1 = __expf(p1 + slp1 * rel);
            const float e2 = __expf(p2 + slp2 * rel);
            const float e3 = __expf(p3 + slp3 * rel);
            l0 += e0; l1 += e1; l2 += e2; l3 += e3;
            a0.x += e0*vA.x; a0.y += e0*vA.y; a0.z += e0*vA.z; a0.w += e0*vA.w;
            a1.x += e1*vA.x; a1.y += e1*vA.y; a1.z += e1*vA.z; a1.w += e1*vA.w;
            a2.x += e2*vA.x; a2.y += e2*vA.y; a2.z += e2*vA.z; a2.w += e2*vA.w;
            a3.x += e3*vA.x; a3.y += e3*vA.y; a3.z += e3*vA.z; a3.w += e3*vA.w;
        }
        if (okB) {
            float p0 = qr0.x*kB.x + qr0.y*kB.y + qr0.z*kB.z + qr0.w*kB.w;
            float p1 = qr1.x*kB.x + qr1.y*kB.y + qr1.z*kB.z + qr1.w*kB.w;
            float p2 = qr2.x*kB.x + qr2.y*kB.y + qr2.z*kB.z + qr2.w*kB.w;
            float p3 = qr3.x*kB.x + qr3.y*kB.y + qr3.z*kB.z + qr3.w*kB.w;
            #pragma unroll
            for (int off = 16; off > 0; off >>= 1) {
                p0 += __shfl_xor_sync(0xffffffff, p0, off);
                p1 += __shfl_xor_sync(0xffffffff, p1, off);
                p2 += __shfl_xor_sync(0xffffffff, p2, off);
                p3 += __shfl_xor_sync(0xffffffff, p3, off);
            }
            const float rel = relbase + (float)tlB;
            const float e0 = __expf(p0 + slp0 * rel);
            const float e1 = __expf(p1 + slp1 * rel);
            const float e2 = __expf(p2 + slp2 * rel);
            const float e3 = __expf(p3 + slp3 * rel);
            l0 += e0; l1 += e1; l2 += e2; l3 += e3;
            a0.x += e0*vB.x; a0.y += e0*vB.y; a0.z += e0*vB.z; a0.w += e0*vB.w;
            a1.x += e1*vB.x; a1.y += e1*vB.y; a1.z += e1*vB.z; a1.w += e1*vB.w;
            a2.x += e2*vB.x; a2.y += e2*vB.y; a2.z += e2*vB.z; a2.w += e2*vB.w;
            a3.x += e3*vB.x; a3.y += e3*vB.y; a3.z += e3*vB.z; a3.w += e3*vB.w;
        }
    }

    // Cross-warp reduction
    if (lane == 0) { wl[warp][0] = l0; wl[warp][1] = l1; wl[warp][2] = l2; wl[warp][3] = l3; }
    ((float4*)&red[warp][0][0])[lane] = a0;
    ((float4*)&red[warp][1][0])[lane] = a1;
    ((float4*)&red[warp][2][0])[lane] = a2;
    ((float4*)&red[warp][3][0])[lane] = a3;
    __syncthreads();

    const int d  = tid & 127;
    const int g0 = tid >> 7;
    float r0 = 0.f, r1 = 0.f;
    #pragma unroll
    for (int w = 0; w < NWARPS; w++) {
        r0 += red[w][g0][d];
        r1 += red[w][g0 + 2][d];
    }

    const size_t pb = ((size_t)(s * KVH + kv) * NP + p) * GQ;
    g_pacc[(pb + g0)     * HD + d] = r0;
    g_pacc[(pb + g0 + 2) * HD + d] = r1;
    if (tid < GQ) {
        float L = 0.f;
        #pragma unroll
        for (int w = 0; w < NWARPS; w++) L += wl[w][tid];
        g_pl[pb + tid] = L;
    }
}

__global__ __launch_bounds__(128)
void paged_attn_reduce_kernel(const int* __restrict__ seqlen,
                              float* __restrict__ out)
{
    const int s    = blockIdx.x / KVH;
    const int kv   = blockIdx.x % KVH;
    const int g    = threadIdx.x >> 5;     // head within group
    const int lane = threadIdx.x & 31;     // float4 index over HD

    const int len = seqlen[s];
    const int np  = (len + PART - 1) / PART;
    const size_t base = (size_t)(s * KVH + kv) * NP * GQ;

    float4 o = {0,0,0,0};
    float  L = 0.f;
    for (int p = 0; p < np; p++) {
        const size_t idx = base + (size_t)p * GQ + g;
        const float4 a = ((const float4*)g_pacc)[idx * (HD/4) + lane];
        L += g_pl[idx];
        o.x += a.x; o.y += a.y; o.z += a.z; o.w += a.w;
    }
    const float inv = 1.0f / L;
    o.x *= inv; o.y *= inv; o.z *= inv; o.w *= inv;
    ((float4*)out)[(size_t)(s * NUM_HEADS + kv * GQ + g) * (HD/4) + lane] = o;
}

extern "C" void kernel_launch(void* const* d_in, const int* in_sizes, int n_in,
                              void* d_out, int out_size) {
    const float* query       = (const float*)d_in[0];
    const float* key_cache   = (const float*)d_in[1];
    const float* value_cache = (const float*)d_in[2];
    const float* scale       = (const float*)d_in[4];
    const int*   block_tab   = (const int*)  d_in[5];
    const int*   seq_lens    = (const int*)  d_in[6];
    const float* alibi       = (const float*)d_in[9];
    float* out = (float*)d_out;

    paged_attn_part_kernel<<<NUM_SEQS * KVH * NP, NTHREADS>>>(
        query, key_cache, value_cache, scale, block_tab, seq_lens, alibi);
    paged_attn_reduce_kernel<<<NUM_SEQS * KVH, 128>>>(seq_lens, out);
}